// round 11
// baseline (speedup 1.0000x reference)
#include <cuda_runtime.h>
#include <cstdint>

// ---------------------------------------------------------------------------
// ConvKanModel: persistent FFMA2 oc-pair conv, occupancy-3, double-buffered
// channel pipeline. Per channel iteration: prefetch inputs(c+1) + weight-copy
// (c+1) -> compute(c) -> feature math+STS(c+1) -> ONE barrier. Staging math
// overlaps compute across warps (no barrier between phases); LDG latency
// hidden behind the FFMA2 block.
// ---------------------------------------------------------------------------

#define NB      4
#define CCH     16
#define KB      11
#define JF      12
#define HW      512
#define PLANE   (HW*HW)
#define TOTAL   (NB*CCH*PLANE)

#define TW      32
#define TH      16
#define HALOW   34
#define HALOH   18
#define HALO2   (HALOW*HALOH)     // 612
#define NW      (JF*3*3*CCH)      // 1728
#define ABUF    (JF*HALO2)        // 7344 words
#define NTILES  ((HW/TW)*(HW/TH)*NB)   // 2048
#define SMEM_WORDS (2*ABUF + 2*NW)     // 18144
#define SMEM_BYTES (SMEM_WORDS*4)      // 72576

#define GRID_P  444               // persistent CTAs (3 per SM)

__device__ float g_z1[TOTAL];
__device__ float g_z2[TOTAL];
__device__ float g_m1[64], g_r1[64], g_m2[64], g_r2[64];
__device__ unsigned int g_ctr[2];

typedef unsigned long long u64;

__device__ __forceinline__ u64 pack2(float x) {
    u64 r;
    asm("mov.b64 %0, {%1, %1};" : "=l"(r) : "f"(x));
    return r;
}
__device__ __forceinline__ void fma2(u64& d, u64 a, u64 b) {
    asm("fma.rn.f32x2 %0, %1, %2, %0;" : "+l"(d) : "l"(a), "l"(b));
}

__global__ void reset_ctr() {
    if (threadIdx.x < 2) g_ctr[threadIdx.x] = 0u;
}

// feature math + scatter into planar smem buffer for one halo index
template<bool NORM>
__device__ __forceinline__ void feat_store(float* s_act, int idx, bool inb,
                                           float x, float mu, float rs,
                                           float alpha)
{
    float a0 = 0.0f, w0 = 0.0f, w1 = 0.0f, w2 = 0.0f, w3 = 0.0f;
    int cell = -100;
    if (inb) {
        if (NORM) {
            x = (x - mu) * rs;
            x = (x < 0.0f) ? alpha * x : x;        // prelu
        }
        a0 = x / (1.0f + __expf(-x));              // silu
        const float u  = (x + 1.75f) * 4.0f;
        const float cf = floorf(u);
        const int   ci = (int)cf;
        if (ci >= 0 && ci < 14) {
            cell = ci;
            const float t = u - cf, mt = 1.0f - t, t2 = t*t, t3 = t2*t;
            w0 = mt*mt*mt * (1.0f/6.0f);
            w1 = (3.0f*t3 - 6.0f*t2 + 4.0f) * (1.0f/6.0f);
            w2 = (-3.0f*t3 + 3.0f*t2 + 3.0f*t + 1.0f) * (1.0f/6.0f);
            w3 = t3 * (1.0f/6.0f);
        }
    }
    s_act[idx] = a0;                               // feature 0 = silu
#pragma unroll
    for (int j = 1; j < JF; ++j) s_act[j*HALO2 + idx] = 0.0f;
    if (cell >= 0) {
        // stored bases 0..10 live in slots j = basis+1
        if (cell >= 3)               s_act[(cell-2)*HALO2 + idx] = w0;
        if (cell >= 2 && cell <= 12) s_act[(cell-1)*HALO2 + idx] = w1;
        if (cell >= 1 && cell <= 11) s_act[(cell  )*HALO2 + idx] = w2;
        if (cell <= 10)              s_act[(cell+1)*HALO2 + idx] = w3;
    }
}

// ---------------------------------------------------------------------------
// Persistent fused KAN conv. 256 threads; steals 32x16 tiles.
// tid: col = tid&31, rowgrp = (tid>>5)&3 (4 rows), ohalf = tid>>7 (8 oc).
// ---------------------------------------------------------------------------
template<bool NORM>
__global__ __launch_bounds__(256, 3)
void conv_kan_p(const float* __restrict__ in,
                const float* __restrict__ base_w,    // [16][16][3][3]
                const float* __restrict__ spline_w,  // [16][176][3][3]
                const float* __restrict__ mean,
                const float* __restrict__ rstd,
                const float* __restrict__ alpha_p,
                float* __restrict__ out)
{
    extern __shared__ float smem[];
    float* s_actb[2] = { smem, smem + ABUF };
    float* s_wb[2]   = { smem + 2*ABUF, smem + 2*ABUF + NW };
    __shared__ int s_tile;

    const int tid    = threadIdx.x;
    const int col    = tid & 31;
    const int rowgrp = (tid >> 5) & 3;
    const int ohalf  = tid >> 7;
    const float alpha = NORM ? alpha_p[0] : 0.0f;
    const int ctr_idx = NORM ? 1 : 0;

    // weight-copy decode for this thread's NW elements (constant per thread)
    for (;;) {
        __syncthreads();
        if (tid == 0) s_tile = (int)atomicAdd(&g_ctr[ctr_idx], 1u);
        __syncthreads();
        const int t = s_tile;
        if (t >= NTILES) break;

        const int bx = (t & 15) * TW;
        const int by = ((t >> 4) & 31) * TH;
        const int b  = t >> 9;

        // halo coords for this thread's 3 staging slots
        int h_iy[3], h_ix[3]; bool h_in[3];
#pragma unroll
        for (int it = 0; it < 3; ++it) {
            const int idx = tid + it*256;
            const int iy = idx / HALOW;
            const int ix = idx - iy * HALOW;
            h_iy[it] = by + iy - 1;
            h_ix[it] = bx + ix - 1;
            h_in[it] = (idx < HALO2) && h_iy[it] >= 0 && h_iy[it] < HW
                                     && h_ix[it] >= 0 && h_ix[it] < HW;
        }

        u64 acc[4][4];
#pragma unroll
        for (int r = 0; r < 4; ++r)
#pragma unroll
            for (int p = 0; p < 4; ++p) acc[r][p] = 0ull;

        // ---- prologue: stage channel 0 into buf 0 ----
        {
            const float* inp = in + ((size_t)(b*CCH + 0)) * PLANE;
            float mu = 0.0f, rs = 0.0f;
            if (NORM) { mu = mean[b*CCH]; rs = rstd[b*CCH]; }
#pragma unroll
            for (int it = 0; it < 3; ++it) {
                const int idx = tid + it*256;
                if (idx < HALO2) {
                    const float x = h_in[it] ? inp[h_iy[it]*HW + h_ix[it]] : 0.0f;
                    feat_store<NORM>(s_actb[0], idx, h_in[it], x, mu, rs, alpha);
                }
            }
            for (int idx = tid; idx < NW; idx += 256) {
                const int o    = idx & 15;
                const int rest = idx >> 4;
                const int kx   = rest % 3;
                const int ky   = (rest / 3) % 3;
                const int j    = rest / 9;
                float w;
                if (j == 0) w = base_w[((o*CCH + 0)*3 + ky)*3 + kx];
                else        w = spline_w[((o*(CCH*KB) + (0*KB + j - 1))*3 + ky)*3 + kx];
                s_wb[0][((j*3 + ky)*3 + kx)*CCH + o] = w;
            }
        }
        __syncthreads();

        for (int c = 0; c < CCH; ++c) {
            const int cur = c & 1;
            const float* s_act = s_actb[cur];
            const float* s_w   = s_wb[cur];
            const bool more = (c + 1 < CCH);

            // ---- 1. prefetch inputs for c+1; start weight copy c+1 ----
            float pre[3];
            float muN = 0.0f, rsN = 0.0f;
            if (more) {
                const float* inpN = in + ((size_t)(b*CCH + c + 1)) * PLANE;
                if (NORM) { muN = mean[b*CCH + c + 1]; rsN = rstd[b*CCH + c + 1]; }
#pragma unroll
                for (int it = 0; it < 3; ++it)
                    pre[it] = h_in[it] ? inpN[h_iy[it]*HW + h_ix[it]] : 0.0f;
                // weight copy (LDG latency overlaps the compute below via MLP)
                float* wd = s_wb[1 - cur];
                const int cN = c + 1;
#pragma unroll
                for (int itw = 0; itw < 7; ++itw) {
                    const int idx = tid + itw*256;
                    if (idx < NW) {
                        const int o    = idx & 15;
                        const int rest = idx >> 4;
                        const int kx   = rest % 3;
                        const int ky   = (rest / 3) % 3;
                        const int j    = rest / 9;
                        float w;
                        if (j == 0) w = base_w[((o*CCH + cN)*3 + ky)*3 + kx];
                        else        w = spline_w[((o*(CCH*KB) + (cN*KB + j - 1))*3 + ky)*3 + kx];
                        wd[((j*3 + ky)*3 + kx)*CCH + o] = w;
                    }
                }
            }

            // ---- 2. compute channel c ----
            const int rbase = rowgrp * 4;
#pragma unroll 1
            for (int j = 0; j < JF; ++j) {
                const float* actj = s_act + j*HALO2;
                const float* wj   = s_w + j*9*CCH + ohalf*8;
#pragma unroll
                for (int ky = 0; ky < 3; ++ky) {
                    u64 wv[3][4];
#pragma unroll
                    for (int kx = 0; kx < 3; ++kx) {
                        const u64* wp =
                            reinterpret_cast<const u64*>(wj + (ky*3 + kx)*CCH);
#pragma unroll
                        for (int p = 0; p < 4; ++p) wv[kx][p] = wp[p];
                    }
                    const float* arow = actj + (rbase + ky)*HALOW + col;
#pragma unroll
                    for (int kx = 0; kx < 3; ++kx) {
#pragma unroll
                        for (int r = 0; r < 4; ++r) {
                            const u64 a2 = pack2(arow[r*HALOW + kx]);
#pragma unroll
                            for (int p = 0; p < 4; ++p)
                                fma2(acc[r][p], a2, wv[kx][p]);
                        }
                    }
                }
            }

            // ---- 3. feature math + STS for c+1 (other buffer) ----
            if (more) {
                float* ad = s_actb[1 - cur];
#pragma unroll
                for (int it = 0; it < 3; ++it) {
                    const int idx = tid + it*256;
                    if (idx < HALO2)
                        feat_store<NORM>(ad, idx, h_in[it], pre[it], muN, rsN, alpha);
                }
            }
            // ---- 4. single barrier per channel ----
            __syncthreads();
        }

        // ---- epilogue: 4 pixels x 8 out channels ----
#pragma unroll
        for (int p = 0; p < 4; ++p) {
            const int o0 = ohalf*8 + 2*p;
            float* op0 = out + ((size_t)(b*CCH + o0    )) * PLANE;
            float* op1 = out + ((size_t)(b*CCH + o0 + 1)) * PLANE;
#pragma unroll
            for (int r = 0; r < 4; ++r) {
                const int gy = by + rowgrp*4 + r;
                const uint32_t lo = (uint32_t)(acc[r][p] & 0xffffffffull);
                const uint32_t hi = (uint32_t)(acc[r][p] >> 32);
                op0[gy*HW + bx + col] = __uint_as_float(lo);
                op1[gy*HW + bx + col] = __uint_as_float(hi);
            }
        }
    }
}

// ---------------------------------------------------------------------------
__global__ void stats_kernel(const float* __restrict__ z,
                             float* __restrict__ mean, float* __restrict__ rstd)
{
    __shared__ float sh_s[1024], sh_q[1024];
    const int bc = blockIdx.x;
    const float4* p = reinterpret_cast<const float4*>(z + (size_t)bc * PLANE);
    float s = 0.0f, q = 0.0f;
    for (int i = threadIdx.x; i < PLANE/4; i += 1024) {
        const float4 v = p[i];
        s += v.x + v.y + v.z + v.w;
        q += v.x*v.x + v.y*v.y + v.z*v.z + v.w*v.w;
    }
    sh_s[threadIdx.x] = s; sh_q[threadIdx.x] = q;
    __syncthreads();
    for (int off = 512; off > 0; off >>= 1) {
        if (threadIdx.x < off) {
            sh_s[threadIdx.x] += sh_s[threadIdx.x + off];
            sh_q[threadIdx.x] += sh_q[threadIdx.x + off];
        }
        __syncthreads();
    }
    if (threadIdx.x == 0) {
        const float m = sh_s[0] * (1.0f/PLANE);
        const float v = sh_q[0] * (1.0f/PLANE) - m*m;
        mean[bc] = m; rstd[bc] = rsqrtf(v + 1e-5f);
    }
}

__global__ void finalize_kernel(const float* __restrict__ z,
                                const float* __restrict__ mean,
                                const float* __restrict__ rstd,
                                const float* __restrict__ alpha_p,
                                float* __restrict__ out)
{
    const size_t i4 = (size_t)blockIdx.x * blockDim.x + threadIdx.x;
    if (i4 >= TOTAL/4) return;
    const int bc = (int)(i4 >> 16);
    const float alpha = alpha_p[0], m = mean[bc], rs = rstd[bc];
    float4 v = reinterpret_cast<const float4*>(z)[i4];
    float* vp = &v.x;
#pragma unroll
    for (int k = 0; k < 4; ++k) {
        float t = (vp[k] - m) * rs;
        t = (t < 0.0f) ? alpha * t : t;
        vp[k] = 1.0f / (1.0f + __expf(-t));
    }
    reinterpret_cast<float4*>(out)[i4] = v;
}

// ---------------------------------------------------------------------------
extern "C" void kernel_launch(void* const* d_in, const int* in_sizes, int n_in,
                              void* d_out, int out_size)
{
    const float* x   = (const float*)d_in[0];
    const float* bw1 = (const float*)d_in[1];
    const float* sw1 = (const float*)d_in[2];
    const float* a1  = (const float*)d_in[3];
    const float* bw2 = (const float*)d_in[4];
    const float* sw2 = (const float*)d_in[5];
    const float* a2  = (const float*)d_in[6];
    float* out = (float*)d_out;

    float *z1, *z2, *m1, *r1, *m2, *r2;
    cudaGetSymbolAddress((void**)&z1, g_z1);
    cudaGetSymbolAddress((void**)&z2, g_z2);
    cudaGetSymbolAddress((void**)&m1, g_m1);
    cudaGetSymbolAddress((void**)&r1, g_r1);
    cudaGetSymbolAddress((void**)&m2, g_m2);
    cudaGetSymbolAddress((void**)&r2, g_r2);

    cudaFuncSetAttribute(conv_kan_p<false>,
                         cudaFuncAttributeMaxDynamicSharedMemorySize, SMEM_BYTES);
    cudaFuncSetAttribute(conv_kan_p<true>,
                         cudaFuncAttributeMaxDynamicSharedMemorySize, SMEM_BYTES);

    reset_ctr<<<1, 32>>>();

    conv_kan_p<false><<<GRID_P, 256, SMEM_BYTES>>>(
        x, bw1, sw1, nullptr, nullptr, nullptr, z1);
    stats_kernel<<<NB*CCH, 1024>>>(z1, m1, r1);

    conv_kan_p<true><<<GRID_P, 256, SMEM_BYTES>>>(
        z1, bw2, sw2, m1, r1, a1, z2);
    stats_kernel<<<NB*CCH, 1024>>>(z2, m2, r2);

    finalize_kernel<<<(TOTAL/4 + 255)/256, 256>>>(z2, m2, r2, a2, out);
}

// round 12
// speedup vs baseline: 1.1772x; 1.1772x over previous
#include <cuda_runtime.h>
#include <cstdint>

// ---------------------------------------------------------------------------
// ConvKanModel: persistent FFMA2 oc-pair conv, occupancy-3 (round-10 winner)
// with weight loads widened to LDS128 (ulonglong2): per (j,ky) 6 LDS128
// replace 12 LDS64. Compute-phase crossbar demand drops from parity with the
// fma pipe (20.7K cyc/ch/SM each) to ~15.5K, unblocking the FFMA2 stream.
// ---------------------------------------------------------------------------

#define NB      4
#define CCH     16
#define KB      11
#define JF      12
#define HW      512
#define PLANE   (HW*HW)
#define TOTAL   (NB*CCH*PLANE)

#define TW      32                // tile width
#define TH      16                // tile height
#define HALOW   34
#define HALOH   18
#define HALO2   (HALOW*HALOH)     // 612
#define NW      (JF*3*3*CCH)      // 1728
#define NTILES  ((HW/TW)*(HW/TH)*NB)   // 2048
#define SMEM_BYTES ((JF*HALO2 + NW) * 4)   // 36288

#define GRID_P  444               // persistent CTAs (3 per SM)

__device__ float g_z1[TOTAL];
__device__ float g_z2[TOTAL];
__device__ float g_m1[64], g_r1[64], g_m2[64], g_r2[64];
__device__ unsigned int g_ctr[2];

typedef unsigned long long u64;

__device__ __forceinline__ u64 pack2(float x) {
    u64 r;
    asm("mov.b64 %0, {%1, %1};" : "=l"(r) : "f"(x));
    return r;
}
__device__ __forceinline__ void fma2(u64& d, u64 a, u64 b) {
    asm("fma.rn.f32x2 %0, %1, %2, %0;" : "+l"(d) : "l"(a), "l"(b));
}

__global__ void reset_ctr() {
    if (threadIdx.x < 2) g_ctr[threadIdx.x] = 0u;
}

// ---------------------------------------------------------------------------
// Persistent fused KAN conv. 256 threads; steals 32x16 tiles (16 oc each).
// tid: col = tid&31, rowgrp = (tid>>5)&3 (4 rows each), ohalf = tid>>7.
// ---------------------------------------------------------------------------
template<bool NORM>
__global__ __launch_bounds__(256, 3)
void conv_kan_p(const float* __restrict__ in,
                const float* __restrict__ base_w,    // [16][16][3][3]
                const float* __restrict__ spline_w,  // [16][176][3][3]
                const float* __restrict__ mean,
                const float* __restrict__ rstd,
                const float* __restrict__ alpha_p,
                float* __restrict__ out)
{
    extern __shared__ float smem[];
    float* s_act = smem;                 // [JF][612]
    float* s_w   = smem + JF*HALO2;      // [JF][3][3][16]
    __shared__ int s_tile;

    const int tid    = threadIdx.x;
    const int col    = tid & 31;
    const int rowgrp = (tid >> 5) & 3;
    const int ohalf  = tid >> 7;
    const float alpha = NORM ? alpha_p[0] : 0.0f;
    const int ctr_idx = NORM ? 1 : 0;

    for (;;) {
        __syncthreads();   // protect s_tile + previous tile's smem reads
        if (tid == 0) s_tile = (int)atomicAdd(&g_ctr[ctr_idx], 1u);
        __syncthreads();
        const int t = s_tile;
        if (t >= NTILES) break;

        const int bx = (t & 15) * TW;
        const int by = ((t >> 4) & 31) * TH;
        const int b  = t >> 9;

        u64 acc[4][4];
#pragma unroll
        for (int r = 0; r < 4; ++r)
#pragma unroll
            for (int p = 0; p < 4; ++p) acc[r][p] = 0ull;

        for (int c = 0; c < CCH; ++c) {
            __syncthreads();   // protect previous channel's smem reads

            // ---- build activation tile for input channel c ----
            const float* inp = in + ((size_t)(b*CCH + c)) * PLANE;
            float mu = 0.0f, rs = 0.0f;
            if (NORM) { mu = mean[b*CCH + c]; rs = rstd[b*CCH + c]; }

#pragma unroll
            for (int it = 0; it < 3; ++it) {
                const int idx = tid + it*256;
                if (idx >= HALO2) break;
                const int iy = idx / HALOW;
                const int ix = idx - iy * HALOW;
                const int gy = by + iy - 1;
                const int gx = bx + ix - 1;

                float a0 = 0.0f, w0 = 0.0f, w1 = 0.0f, w2 = 0.0f, w3 = 0.0f;
                int cell = -100;
                if (gy >= 0 && gy < HW && gx >= 0 && gx < HW) {
                    float x = inp[gy*HW + gx];
                    if (NORM) {
                        x = (x - mu) * rs;
                        x = (x < 0.0f) ? alpha * x : x;   // prelu
                    }
                    a0 = x / (1.0f + __expf(-x));          // silu
                    const float u  = (x + 1.75f) * 4.0f;
                    const float cf = floorf(u);
                    const int ci = (int)cf;
                    if (ci >= 0 && ci < 14) {
                        cell = ci;
                        const float tt = u - cf;
                        const float mt = 1.0f - tt;
                        const float t2 = tt*tt, t3 = t2*tt;
                        w0 = mt*mt*mt * (1.0f/6.0f);
                        w1 = (3.0f*t3 - 6.0f*t2 + 4.0f) * (1.0f/6.0f);
                        w2 = (-3.0f*t3 + 3.0f*t2 + 3.0f*tt + 1.0f) * (1.0f/6.0f);
                        w3 = t3 * (1.0f/6.0f);
                    }
                }
                s_act[idx] = a0;                     // feature 0 = silu
#pragma unroll
                for (int j = 1; j < JF; ++j) s_act[j*HALO2 + idx] = 0.0f;
                if (cell >= 0) {
                    // stored bases 0..10 live in slots j = basis+1
                    if (cell >= 3)               s_act[(cell-2)*HALO2 + idx] = w0;
                    if (cell >= 2 && cell <= 12) s_act[(cell-1)*HALO2 + idx] = w1;
                    if (cell >= 1 && cell <= 11) s_act[(cell  )*HALO2 + idx] = w2;
                    if (cell <= 10)              s_act[(cell+1)*HALO2 + idx] = w3;
                }
            }

            // ---- load combined weights for channel c: [j][ky][kx][o] ----
#pragma unroll
            for (int it = 0; it < 7; ++it) {
                const int idx = tid + it*256;
                if (idx >= NW) break;
                const int o    = idx & 15;
                const int rest = idx >> 4;
                const int kx   = rest % 3;
                const int ky   = (rest / 3) % 3;
                const int j    = rest / 9;
                float w;
                if (j == 0) w = base_w[((o*CCH + c)*3 + ky)*3 + kx];
                else        w = spline_w[((o*(CCH*KB) + (c*KB + j - 1))*3 + ky)*3 + kx];
                s_w[((j*3 + ky)*3 + kx)*CCH + o] = w;
            }
            __syncthreads();

            // ---- accumulate: 12 features x 9 taps, oc-pair packed ----
            const int rbase = rowgrp * 4;
#pragma unroll 1
            for (int j = 0; j < JF; ++j) {
                const float* actj = s_act + j*HALO2;
                const float* wj   = s_w + j*9*CCH + ohalf*8;
#pragma unroll
                for (int ky = 0; ky < 3; ++ky) {
                    // hoist 12 weight pairs for this (j,ky) via 6 LDS128
                    u64 wv[3][4];
#pragma unroll
                    for (int kx = 0; kx < 3; ++kx) {
                        const ulonglong2* wp =
                            reinterpret_cast<const ulonglong2*>(wj + (ky*3 + kx)*CCH);
                        const ulonglong2 w01 = wp[0];
                        const ulonglong2 w23 = wp[1];
                        wv[kx][0] = w01.x; wv[kx][1] = w01.y;
                        wv[kx][2] = w23.x; wv[kx][3] = w23.y;
                    }
                    const float* arow = actj + (rbase + ky)*HALOW + col;
#pragma unroll
                    for (int kx = 0; kx < 3; ++kx) {
#pragma unroll
                        for (int r = 0; r < 4; ++r) {
                            const u64 a2 = pack2(arow[r*HALOW + kx]);
#pragma unroll
                            for (int p = 0; p < 4; ++p)
                                fma2(acc[r][p], a2, wv[kx][p]);
                        }
                    }
                }
            }
        }

        // ---- epilogue: unpack & write 4 pixels x 8 out channels ----
#pragma unroll
        for (int p = 0; p < 4; ++p) {
            const int o0 = ohalf*8 + 2*p;
            float* op0 = out + ((size_t)(b*CCH + o0    )) * PLANE;
            float* op1 = out + ((size_t)(b*CCH + o0 + 1)) * PLANE;
#pragma unroll
            for (int r = 0; r < 4; ++r) {
                const int gy = by + rowgrp*4 + r;
                const uint32_t lo = (uint32_t)(acc[r][p] & 0xffffffffull);
                const uint32_t hi = (uint32_t)(acc[r][p] >> 32);
                op0[gy*HW + bx + col] = __uint_as_float(lo);
                op1[gy*HW + bx + col] = __uint_as_float(hi);
            }
        }
    }
}

// ---------------------------------------------------------------------------
__global__ void stats_kernel(const float* __restrict__ z,
                             float* __restrict__ mean, float* __restrict__ rstd)
{
    __shared__ float sh_s[1024], sh_q[1024];
    const int bc = blockIdx.x;
    const float4* p = reinterpret_cast<const float4*>(z + (size_t)bc * PLANE);
    float s = 0.0f, q = 0.0f;
    for (int i = threadIdx.x; i < PLANE/4; i += 1024) {
        const float4 v = p[i];
        s += v.x + v.y + v.z + v.w;
        q += v.x*v.x + v.y*v.y + v.z*v.z + v.w*v.w;
    }
    sh_s[threadIdx.x] = s; sh_q[threadIdx.x] = q;
    __syncthreads();
    for (int off = 512; off > 0; off >>= 1) {
        if (threadIdx.x < off) {
            sh_s[threadIdx.x] += sh_s[threadIdx.x + off];
            sh_q[threadIdx.x] += sh_q[threadIdx.x + off];
        }
        __syncthreads();
    }
    if (threadIdx.x == 0) {
        const float m = sh_s[0] * (1.0f/PLANE);
        const float v = sh_q[0] * (1.0f/PLANE) - m*m;
        mean[bc] = m; rstd[bc] = rsqrtf(v + 1e-5f);
    }
}

__global__ void finalize_kernel(const float* __restrict__ z,
                                const float* __restrict__ mean,
                                const float* __restrict__ rstd,
                                const float* __restrict__ alpha_p,
                                float* __restrict__ out)
{
    const size_t i4 = (size_t)blockIdx.x * blockDim.x + threadIdx.x;
    if (i4 >= TOTAL/4) return;
    const int bc = (int)(i4 >> 16);
    const float alpha = alpha_p[0], m = mean[bc], rs = rstd[bc];
    float4 v = reinterpret_cast<const float4*>(z)[i4];
    float* vp = &v.x;
#pragma unroll
    for (int k = 0; k < 4; ++k) {
        float t = (vp[k] - m) * rs;
        t = (t < 0.0f) ? alpha * t : t;
        vp[k] = 1.0f / (1.0f + __expf(-t));
    }
    reinterpret_cast<float4*>(out)[i4] = v;
}

// ---------------------------------------------------------------------------
extern "C" void kernel_launch(void* const* d_in, const int* in_sizes, int n_in,
                              void* d_out, int out_size)
{
    const float* x   = (const float*)d_in[0];
    const float* bw1 = (const float*)d_in[1];
    const float* sw1 = (const float*)d_in[2];
    const float* a1  = (const float*)d_in[3];
    const float* bw2 = (const float*)d_in[4];
    const float* sw2 = (const float*)d_in[5];
    const float* a2  = (const float*)d_in[6];
    float* out = (float*)d_out;

    float *z1, *z2, *m1, *r1, *m2, *r2;
    cudaGetSymbolAddress((void**)&z1, g_z1);
    cudaGetSymbolAddress((void**)&z2, g_z2);
    cudaGetSymbolAddress((void**)&m1, g_m1);
    cudaGetSymbolAddress((void**)&r1, g_r1);
    cudaGetSymbolAddress((void**)&m2, g_m2);
    cudaGetSymbolAddress((void**)&r2, g_r2);

    cudaFuncSetAttribute(conv_kan_p<false>,
                         cudaFuncAttributeMaxDynamicSharedMemorySize, SMEM_BYTES);
    cudaFuncSetAttribute(conv_kan_p<true>,
                         cudaFuncAttributeMaxDynamicSharedMemorySize, SMEM_BYTES);

    reset_ctr<<<1, 32>>>();

    conv_kan_p<false><<<GRID_P, 256, SMEM_BYTES>>>(
        x, bw1, sw1, nullptr, nullptr, nullptr, z1);
    stats_kernel<<<NB*CCH, 1024>>>(z1, m1, r1);

    conv_kan_p<true><<<GRID_P, 256, SMEM_BYTES>>>(
        z1, bw2, sw2, m1, r1, a1, z2);
    stats_kernel<<<NB*CCH, 1024>>>(z2, m2, r2);

    finalize_kernel<<<(TOTAL/4 + 255)/256, 256>>>(z2, m2, r2, a2, out);
}